// round 13
// baseline (speedup 1.0000x reference)
#include <cuda_runtime.h>
#include <cuda_fp16.h>
#include <cstdint>

#define BWIN 4096
#define NTOK 49
#define DIM  256
#define NH   8
#define HD   32
#define MTOT (BWIN * NTOK)            /* 200704 */
#define QKV_S (BWIN * NH * NTOK * HD) /* 51380224 */

typedef unsigned long long u64;
typedef unsigned int u32;

// ---------------- device scratch (allocation-free) ----------------
__device__ float g_qkv[3ULL * QKV_S];                       // fp32 [3][B][H][N][hd]
__device__ float g_bias[NH * NTOK * NTOK];                  // [H][N][N]
__device__ __align__(16) __half g_xhi[(size_t)MTOT * DIM];
__device__ __align__(16) __half g_xlo[(size_t)MTOT * DIM];
__device__ __align__(16) __half g_ahi[(size_t)MTOT * DIM];
__device__ __align__(16) __half g_alo[(size_t)MTOT * DIM];
__device__ __align__(16) __half g_wqhi[768 * 256];
__device__ __align__(16) __half g_wphi[256 * 256];

// ---------------- helpers ----------------
__device__ __forceinline__ u64 f2fma(u64 a, u64 b, u64 c) {
    u64 d;
    asm("fma.rn.f32x2 %0, %1, %2, %3;" : "=l"(d) : "l"(a), "l"(b), "l"(c));
    return d;
}
__device__ __forceinline__ u64 dup32(float x) {
    u64 d;
    asm("mov.b64 %0, {%1, %1};" : "=l"(d) : "r"(__float_as_uint(x)));
    return d;
}
__device__ __forceinline__ void split_h(float x, unsigned short& h, unsigned short& l) {
    __half hb = __float2half_rn(x);
    float r = x - __half2float(hb);
    __half lb = __float2half_rn(r);
    h = __half_as_ushort(hb);
    l = __half_as_ushort(lb);
}
__device__ __forceinline__ u32 smem_u32(const void* p) {
    u32 a;
    asm("{ .reg .u64 t; cvta.to.shared.u64 t, %1; cvt.u32.u64 %0, t; }" : "=r"(a) : "l"(p));
    return a;
}

__device__ __forceinline__ void mma16816(float* d, u32 a0, u32 a1, u32 a2, u32 a3,
                                         u32 b0, u32 b1) {
    asm volatile(
        "mma.sync.aligned.m16n8k16.row.col.f32.f16.f16.f32 "
        "{%0,%1,%2,%3}, {%4,%5,%6,%7}, {%8,%9}, {%0,%1,%2,%3};"
        : "+f"(d[0]), "+f"(d[1]), "+f"(d[2]), "+f"(d[3])
        : "r"(a0), "r"(a1), "r"(a2), "r"(a3), "r"(b0), "r"(b1));
}

#define LDSM_X4(r0, r1, r2, r3, addr) \
    asm volatile("ldmatrix.sync.aligned.m8n8.x4.shared.b16 {%0,%1,%2,%3}, [%4];" \
        : "=r"(r0), "=r"(r1), "=r"(r2), "=r"(r3) : "r"(addr))

#define CP_ASYNC16(s, g) \
    asm volatile("cp.async.cg.shared.global [%0], [%1], 16;" :: "r"(s), "l"(g))
#define CP_COMMIT() asm volatile("cp.async.commit_group;" ::: "memory")
#define CP_WAITG(n) asm volatile("cp.async.wait_group %0;" :: "n"(n) : "memory")

// ---------------- kernel: bias gather ----------------
__global__ void bias_kernel(const float* __restrict__ table, const int* __restrict__ rel) {
    int idx = blockIdx.x * 256 + threadIdx.x;
    if (idx < NH * NTOK * NTOK) {
        int h = idx / (NTOK * NTOK);
        int nm = idx - h * (NTOK * NTOK);
        g_bias[idx] = table[rel[nm] * NH + h];
    }
}

// ---------------- kernels: fp32 -> fp16 hi/lo ----------------
__global__ void conv_x(const float* __restrict__ x) {
    size_t i = (size_t)blockIdx.x * 256 + threadIdx.x;
    if (i < (size_t)MTOT * DIM / 4) {
        float4 v = ((const float4*)x)[i];
        unsigned short h0, h1, h2, h3, l0, l1, l2, l3;
        split_h(v.x, h0, l0); split_h(v.y, h1, l1);
        split_h(v.z, h2, l2); split_h(v.w, h3, l3);
        ((uint2*)g_xhi)[i] = make_uint2((u32)h0 | ((u32)h1 << 16), (u32)h2 | ((u32)h3 << 16));
        ((uint2*)g_xlo)[i] = make_uint2((u32)l0 | ((u32)l1 << 16), (u32)l2 | ((u32)l3 << 16));
    }
}
__global__ void conv_w(const float* __restrict__ wq, const float* __restrict__ wp) {
    int i = blockIdx.x * 256 + threadIdx.x;
    const int nq4 = 768 * 256 / 4;
    const int np4 = 256 * 256 / 4;
    if (i < nq4) {
        float4 v = ((const float4*)wq)[i];
        ((uint2*)g_wqhi)[i] = make_uint2(
            (u32)__half_as_ushort(__float2half_rn(v.x)) | ((u32)__half_as_ushort(__float2half_rn(v.y)) << 16),
            (u32)__half_as_ushort(__float2half_rn(v.z)) | ((u32)__half_as_ushort(__float2half_rn(v.w)) << 16));
    } else if (i < nq4 + np4) {
        int j = i - nq4;
        float4 v = ((const float4*)wp)[j];
        ((uint2*)g_wphi)[j] = make_uint2(
            (u32)__half_as_ushort(__float2half_rn(v.x)) | ((u32)__half_as_ushort(__float2half_rn(v.y)) << 16),
            (u32)__half_as_ushort(__float2half_rn(v.z)) | ((u32)__half_as_ushort(__float2half_rn(v.w)) << 16));
    }
}

// -------- tensor-core GEMM (fp16 2-term: Ah*Bh + Al*Bh; K32 3-stage ring) --------
#define KC      32
#define RSTRIDE 40
#define TILE_E  (128 * RSTRIDE)
#define TILE_B  (TILE_E * 2)
#define STAGE_B (3 * TILE_B)
#define NSTAGE  3
#define SMEM_BYTES (NSTAGE * STAGE_B)

template <int MODE>
__global__ __launch_bounds__(256)
void gemm_mma(const float* __restrict__ bias, float* __restrict__ out) {
    extern __shared__ __half sm[];

    const __half* Ah = MODE ? g_ahi : g_xhi;
    const __half* Al = MODE ? g_alo : g_xlo;
    const __half* Bh = MODE ? g_wphi : g_wqhi;

    const int tid  = threadIdx.x;
    const int warp = tid >> 5;
    const int lane = tid & 31;
    const int g    = lane >> 2;
    const int t4   = lane & 3;
    const int wm   = warp >> 2;
    const int wn   = warp & 3;

    const int    o0 = blockIdx.x * 128;
    const size_t m0 = (size_t)blockIdx.y * 128;

    const u32 smem_base = smem_u32(sm);

    const int row0 = tid >> 2;
    const int row1 = row0 + 64;
    const int seg  = (tid & 3) * 8;

    const __half* gA0h = Ah + (m0 + row0) * 256 + seg;
    const __half* gA1h = Ah + (m0 + row1) * 256 + seg;
    const __half* gA0l = Al + (m0 + row0) * 256 + seg;
    const __half* gA1l = Al + (m0 + row1) * 256 + seg;
    const __half* gB0h = Bh + (size_t)(o0 + row0) * 256 + seg;
    const __half* gB1h = Bh + (size_t)(o0 + row1) * 256 + seg;

    const u32 s0b = (u32)(row0 * RSTRIDE + seg) * 2;
    const u32 s1b = (u32)(row1 * RSTRIDE + seg) * 2;

    const int q3 = (lane >> 3) & 1;
    const int q4 = (lane >> 4) & 1;
    const int r8 = lane & 7;
    const u32 offA  = 0 * TILE_B + (u32)(((wm * 64 + q3 * 8 + r8) * RSTRIDE) + q4 * 8) * 2;
    const u32 offB0 = 2 * TILE_B + (u32)(((wn * 32 + 0 * 16 + q4 * 8 + r8) * RSTRIDE) + q3 * 8) * 2;
    const u32 offB1 = 2 * TILE_B + (u32)(((wn * 32 + 1 * 16 + q4 * 8 + r8) * RSTRIDE) + q3 * 8) * 2;

    float acc[4][4][4];
#pragma unroll
    for (int a = 0; a < 4; ++a)
#pragma unroll
        for (int b = 0; b < 4; ++b)
#pragma unroll
            for (int c = 0; c < 4; ++c) acc[a][b][c] = 0.f;

#define ISSUE_STAGE(stg, kb) do {                                      \
        const u32 nx = smem_base + (u32)(stg) * STAGE_B;               \
        CP_ASYNC16(nx + 0 * TILE_B + s0b, gA0h + (kb));                \
        CP_ASYNC16(nx + 0 * TILE_B + s1b, gA1h + (kb));                \
        CP_ASYNC16(nx + 1 * TILE_B + s0b, gA0l + (kb));                \
        CP_ASYNC16(nx + 1 * TILE_B + s1b, gA1l + (kb));                \
        CP_ASYNC16(nx + 2 * TILE_B + s0b, gB0h + (kb));                \
        CP_ASYNC16(nx + 2 * TILE_B + s1b, gB1h + (kb));                \
        CP_COMMIT();                                                   \
    } while (0)

    ISSUE_STAGE(0, 0);
    ISSUE_STAGE(1, KC);

    int cur = 0;
#pragma unroll 1
    for (int kc = 0; kc < 8; ++kc) {
        if (kc < 7) CP_WAITG(1);
        else        CP_WAITG(0);
        __syncthreads();

        if (kc + 2 < 8) {
            int nxt = cur + 2; if (nxt >= 3) nxt -= 3;
            ISSUE_STAGE(nxt, (kc + 2) * KC);
        }

        const u32 stb = smem_base + (u32)cur * STAGE_B;
#pragma unroll
        for (int ks = 0; ks < 2; ++ks) {
            const u32 kso = (u32)(ks * 32);
            u32 bh[4][2];
            LDSM_X4(bh[0][0], bh[0][1], bh[1][0], bh[1][1], stb + offB0 + kso);
            LDSM_X4(bh[2][0], bh[2][1], bh[3][0], bh[3][1], stb + offB1 + kso);
#pragma unroll
            for (int mi = 0; mi < 4; ++mi) {
                const u32 ao = stb + offA + (u32)(mi * 16 * RSTRIDE * 2) + kso;
                u32 ah0, ah1, ah2, ah3, al0, al1, al2, al3;
                LDSM_X4(ah0, ah1, ah2, ah3, ao);
                LDSM_X4(al0, al1, al2, al3, ao + TILE_B);
#pragma unroll
                for (int ni = 0; ni < 4; ++ni) {
                    mma16816(acc[mi][ni], ah0, ah1, ah2, ah3, bh[ni][0], bh[ni][1]);
                    mma16816(acc[mi][ni], al0, al1, al2, al3, bh[ni][0], bh[ni][1]);
                }
            }
        }
        if (++cur == 3) cur = 0;
    }
#undef ISSUE_STAGE

    // ---- epilogue: bias add + store straight from registers ----
#pragma unroll
    for (int mi = 0; mi < 4; ++mi) {
        const int r0 = (int)m0 + wm * 64 + mi * 16 + g;
        const int r1 = r0 + 8;
#pragma unroll
        for (int ni = 0; ni < 4; ++ni) {
            const int c = o0 + wn * 32 + ni * 8 + 2 * t4;
            const float b0 = bias[c], b1 = bias[c + 1];
            float v00 = acc[mi][ni][0] + b0, v01 = acc[mi][ni][1] + b1;
            float v10 = acc[mi][ni][2] + b0, v11 = acc[mi][ni][3] + b1;
            if (MODE == 0) {
                const int which = c >> 8;
                const int head  = (c >> 5) & 7;
                const int d     = c & 31;
#pragma unroll
                for (int rr = 0; rr < 2; ++rr) {
                    const int m = rr ? r1 : r0;
                    const int bwin = m / NTOK;
                    const int n = m - bwin * NTOK;
                    float* dst = g_qkv + (size_t)which * QKV_S +
                        (((size_t)bwin * NH + head) * NTOK + n) * HD + d;
                    *(float2*)dst = rr ? make_float2(v10, v11) : make_float2(v00, v01);
                }
            } else {
                *(float2*)(out + (size_t)r0 * 256 + c) = make_float2(v00, v01);
                *(float2*)(out + (size_t)r1 * 256 + c) = make_float2(v10, v11);
            }
        }
    }
}

// ---------------- fused window attention: 128 threads, fine tiles ----------------
// smem: 3 planes of 52x34 (q,k,v) = 21.2 KB; score s[49][50] aliases planes 0-1.
__global__ __launch_bounds__(128)
void attn_kernel() {
    __shared__ __align__(16) float pool[3][52][34];
    float (*sq)[34] = pool[0];
    float (*sk)[34] = pool[1];
    float (*sv)[34] = pool[2];
    float (*s)[50]  = (float (*)[50])&pool[0][0][0];   // 2450 floats <= 2*52*34=3536

    const int tid = threadIdx.x;
    const int bh = blockIdx.x;
    const int bwin = bh >> 3;
    const int h = bh & 7;

    // zero-pad sk rows 49..51 (QK m-tiles overhang to 51)
    if (tid < 102) {
        const int r = 49 + tid / 34, c = tid % 34;
        sk[r][c] = 0.f;
    }

    const size_t base = (size_t)bh * (NTOK * HD);
    const float4* q4 = (const float4*)(g_qkv + base);
    const float4* k4 = (const float4*)(g_qkv + (size_t)QKV_S + base);
    const float4* v4 = (const float4*)(g_qkv + 2ULL * QKV_S + base);

    for (int i = tid; i < NTOK * HD / 4; i += 128) {
        const int r = i >> 3, c = (i & 7) * 4;
        float4 a = q4[i];
        sq[r][c] = a.x; sq[r][c + 1] = a.y; sq[r][c + 2] = a.z; sq[r][c + 3] = a.w;
        float4 b = k4[i];
        sk[r][c] = b.x; sk[r][c + 1] = b.y; sk[r][c + 2] = b.z; sk[r][c + 3] = b.w;
        float4 d = v4[i];
        sv[r][c] = d.x; sv[r][c + 1] = d.y; sv[r][c + 2] = d.z; sv[r][c + 3] = d.w;
    }
    __syncthreads();

    // QK^T: 91 threads, 7(n) x 4(m) register tiles, f32x2 along hd
    u64 acc[7][4];
    int n0 = 0, m0 = 0;
    if (tid < 91) {
        const int ti = tid / 13, tj = tid - ti * 13;
        n0 = ti * 7; m0 = tj * 4;
#pragma unroll
        for (int r = 0; r < 7; ++r)
#pragma unroll
            for (int cc = 0; cc < 4; ++cc) acc[r][cc] = 0ull;
#pragma unroll
        for (int kk = 0; kk < 16; ++kk) {
            u64 qv[7], kv[4];
#pragma unroll
            for (int r = 0; r < 7; ++r) qv[r] = *(const u64*)&sq[n0 + r][2 * kk];
#pragma unroll
            for (int cc = 0; cc < 4; ++cc) kv[cc] = *(const u64*)&sk[m0 + cc][2 * kk];
#pragma unroll
            for (int r = 0; r < 7; ++r)
#pragma unroll
                for (int cc = 0; cc < 4; ++cc) acc[r][cc] = f2fma(qv[r], kv[cc], acc[r][cc]);
        }
    }
    __syncthreads();   // all sq/sk reads done before s (aliased) is written

    if (tid < 91) {
        const float scale = 0.17677669529663687f;
        const float* bb = g_bias + h * (NTOK * NTOK);
#pragma unroll
        for (int r = 0; r < 7; ++r)
#pragma unroll
            for (int cc = 0; cc < 4; ++cc) {
                const int m = m0 + cc;
                if (m < NTOK) {
                    const u64 a = acc[r][cc];
                    const float lo = __uint_as_float((u32)(a & 0xffffffffull));
                    const float hi = __uint_as_float((u32)(a >> 32));
                    s[n0 + r][m] = (lo + hi) * scale + bb[(n0 + r) * NTOK + m];
                }
            }
    }
    __syncthreads();

    // softmax: 98 threads, each handles half a row; combine via shfl with pair lane
    if (tid < 98) {
        const int row = tid >> 1, half = tid & 1;
        const int c0 = half * 25;
        const int cn = half ? 24 : 25;
        const u32 amask = __activemask();
        float mx = -1e30f;
#pragma unroll
        for (int c = 0; c < 25; ++c)
            if (c < cn) mx = fmaxf(mx, s[row][c0 + c]);
        mx = fmaxf(mx, __shfl_xor_sync(amask, mx, 1));
        float sum = 0.f;
#pragma unroll
        for (int c = 0; c < 25; ++c)
            if (c < cn) {
                float e = __expf(s[row][c0 + c] - mx);
                s[row][c0 + c] = e;
                sum += e;
            }
        sum += __shfl_xor_sync(amask, sum, 1);
        const float inv = 1.f / sum;
#pragma unroll
        for (int c = 0; c < 25; ++c)
            if (c < cn) s[row][c0 + c] *= inv;
    }
    __syncthreads();

    // P @ V: 104 threads, 4(n) x 4(d) register tiles, f32x2 along d
    if (tid < 104) {
        const int ti = tid >> 3, tj = tid & 7;     // 13 n-tiles x 8 d-tiles
        const int nn0 = ti * 4, d0 = tj * 4;
        u64 acc2[4][2];
#pragma unroll
        for (int r = 0; r < 4; ++r) { acc2[r][0] = 0ull; acc2[r][1] = 0ull; }
#pragma unroll 7
        for (int m = 0; m < NTOK; ++m) {
            const u64 v0 = *(const u64*)&sv[m][d0];
            const u64 v1 = *(const u64*)&sv[m][d0 + 2];
#pragma unroll
            for (int r = 0; r < 4; ++r) {
                const u64 sd = dup32(s[nn0 + r][m]);   // rows >=49 read pool garbage, discarded
                acc2[r][0] = f2fma(sd, v0, acc2[r][0]);
                acc2[r][1] = f2fma(sd, v1, acc2[r][1]);
            }
        }
#pragma unroll
        for (int r = 0; r < 4; ++r) {
            if (nn0 + r < NTOK) {
                unsigned short hh[4], ll[4];
#pragma unroll
                for (int cc = 0; cc < 2; ++cc) {
                    const u64 a = acc2[r][cc];
                    split_h(__uint_as_float((u32)(a & 0xffffffffull)), hh[2 * cc], ll[2 * cc]);
                    split_h(__uint_as_float((u32)(a >> 32)), hh[2 * cc + 1], ll[2 * cc + 1]);
                }
                uint2 vh = make_uint2((u32)hh[0] | ((u32)hh[1] << 16), (u32)hh[2] | ((u32)hh[3] << 16));
                uint2 vl = make_uint2((u32)ll[0] | ((u32)ll[1] << 16), (u32)ll[2] | ((u32)ll[3] << 16));
                const size_t off = ((size_t)bwin * NTOK + nn0 + r) * 256 + h * 32 + d0;
                *(uint2*)(g_ahi + off) = vh;
                *(uint2*)(g_alo + off) = vl;
            }
        }
    }
}

// ---------------- launch ----------------
extern "C" void kernel_launch(void* const* d_in, const int* in_sizes, int n_in,
                              void* d_out, int out_size) {
    const float* x      = (const float*)d_in[0];
    const float* qkv_w  = (const float*)d_in[1];
    const float* qkv_b  = (const float*)d_in[2];
    const float* proj_w = (const float*)d_in[3];
    const float* proj_b = (const float*)d_in[4];
    const float* table  = (const float*)d_in[5];
    const int*   rel    = (const int*)d_in[6];
    float* out = (float*)d_out;

    static int smem_set = 0;
    if (!smem_set) {
        cudaFuncSetAttribute(gemm_mma<0>, cudaFuncAttributeMaxDynamicSharedMemorySize, SMEM_BYTES);
        cudaFuncSetAttribute(gemm_mma<1>, cudaFuncAttributeMaxDynamicSharedMemorySize, SMEM_BYTES);
        smem_set = 1;
    }

    bias_kernel<<<(NH * NTOK * NTOK + 255) / 256, 256>>>(table, rel);
    conv_x<<<(int)(((size_t)MTOT * DIM / 4 + 255) / 256), 256>>>(x);
    conv_w<<<((768 + 256) * 256 / 4 + 255) / 256, 256>>>(qkv_w, proj_w);
    gemm_mma<0><<<dim3(6, MTOT / 128), 256, SMEM_BYTES>>>(qkv_b, nullptr);
    attn_kernel<<<BWIN * NH, 128>>>();
    gemm_mma<1><<<dim3(2, MTOT / 128), 256, SMEM_BYTES>>>(proj_b, out);
}

// round 14
// speedup vs baseline: 1.1029x; 1.1029x over previous
#include <cuda_runtime.h>
#include <cuda_fp16.h>
#include <cstdint>

#define BWIN 4096
#define NTOK 49
#define DIM  256
#define NH   8
#define HD   32
#define MTOT (BWIN * NTOK)            /* 200704 */
#define QKV_S (BWIN * NH * NTOK * HD) /* 51380224 */

typedef unsigned long long u64;
typedef unsigned int u32;

// ---------------- device scratch (allocation-free) ----------------
__device__ float g_qkv[3ULL * QKV_S];                       // fp32 [3][B][H][N][hd]
__device__ float g_bias[NH * NTOK * NTOK];                  // [H][N][N]
__device__ __align__(16) __half g_xhi[(size_t)MTOT * DIM];
__device__ __align__(16) __half g_xlo[(size_t)MTOT * DIM];
__device__ __align__(16) __half g_ahi[(size_t)MTOT * DIM];
__device__ __align__(16) __half g_alo[(size_t)MTOT * DIM];
__device__ __align__(16) __half g_wqhi[768 * 256];
__device__ __align__(16) __half g_wphi[256 * 256];

// ---------------- helpers ----------------
__device__ __forceinline__ u64 f2fma(u64 a, u64 b, u64 c) {
    u64 d;
    asm("fma.rn.f32x2 %0, %1, %2, %3;" : "=l"(d) : "l"(a), "l"(b), "l"(c));
    return d;
}
__device__ __forceinline__ u64 dup32(float x) {
    u64 d;
    asm("mov.b64 %0, {%1, %1};" : "=l"(d) : "r"(__float_as_uint(x)));
    return d;
}
__device__ __forceinline__ void split_h(float x, unsigned short& h, unsigned short& l) {
    __half hb = __float2half_rn(x);
    float r = x - __half2float(hb);
    __half lb = __float2half_rn(r);
    h = __half_as_ushort(hb);
    l = __half_as_ushort(lb);
}
__device__ __forceinline__ u32 smem_u32(const void* p) {
    u32 a;
    asm("{ .reg .u64 t; cvta.to.shared.u64 t, %1; cvt.u32.u64 %0, t; }" : "=r"(a) : "l"(p));
    return a;
}

__device__ __forceinline__ void mma16816(float* d, u32 a0, u32 a1, u32 a2, u32 a3,
                                         u32 b0, u32 b1) {
    asm volatile(
        "mma.sync.aligned.m16n8k16.row.col.f32.f16.f16.f32 "
        "{%0,%1,%2,%3}, {%4,%5,%6,%7}, {%8,%9}, {%0,%1,%2,%3};"
        : "+f"(d[0]), "+f"(d[1]), "+f"(d[2]), "+f"(d[3])
        : "r"(a0), "r"(a1), "r"(a2), "r"(a3), "r"(b0), "r"(b1));
}

#define LDSM_X4(r0, r1, r2, r3, addr) \
    asm volatile("ldmatrix.sync.aligned.m8n8.x4.shared.b16 {%0,%1,%2,%3}, [%4];" \
        : "=r"(r0), "=r"(r1), "=r"(r2), "=r"(r3) : "r"(addr))

#define CP_ASYNC16(s, g) \
    asm volatile("cp.async.cg.shared.global [%0], [%1], 16;" :: "r"(s), "l"(g))
#define CP_COMMIT() asm volatile("cp.async.commit_group;" ::: "memory")
#define CP_WAITG(n) asm volatile("cp.async.wait_group %0;" :: "n"(n) : "memory")

// ---------------- kernel: bias gather ----------------
__global__ void bias_kernel(const float* __restrict__ table, const int* __restrict__ rel) {
    int idx = blockIdx.x * 256 + threadIdx.x;
    if (idx < NH * NTOK * NTOK) {
        int h = idx / (NTOK * NTOK);
        int nm = idx - h * (NTOK * NTOK);
        g_bias[idx] = table[rel[nm] * NH + h];
    }
}

// ---------------- kernels: fp32 -> fp16 hi/lo ----------------
__global__ void conv_x(const float* __restrict__ x) {
    size_t i = (size_t)blockIdx.x * 256 + threadIdx.x;
    if (i < (size_t)MTOT * DIM / 4) {
        float4 v = ((const float4*)x)[i];
        unsigned short h0, h1, h2, h3, l0, l1, l2, l3;
        split_h(v.x, h0, l0); split_h(v.y, h1, l1);
        split_h(v.z, h2, l2); split_h(v.w, h3, l3);
        ((uint2*)g_xhi)[i] = make_uint2((u32)h0 | ((u32)h1 << 16), (u32)h2 | ((u32)h3 << 16));
        ((uint2*)g_xlo)[i] = make_uint2((u32)l0 | ((u32)l1 << 16), (u32)l2 | ((u32)l3 << 16));
    }
}
__global__ void conv_w(const float* __restrict__ wq, const float* __restrict__ wp) {
    int i = blockIdx.x * 256 + threadIdx.x;
    const int nq4 = 768 * 256 / 4;
    const int np4 = 256 * 256 / 4;
    if (i < nq4) {
        float4 v = ((const float4*)wq)[i];
        ((uint2*)g_wqhi)[i] = make_uint2(
            (u32)__half_as_ushort(__float2half_rn(v.x)) | ((u32)__half_as_ushort(__float2half_rn(v.y)) << 16),
            (u32)__half_as_ushort(__float2half_rn(v.z)) | ((u32)__half_as_ushort(__float2half_rn(v.w)) << 16));
    } else if (i < nq4 + np4) {
        int j = i - nq4;
        float4 v = ((const float4*)wp)[j];
        ((uint2*)g_wphi)[j] = make_uint2(
            (u32)__half_as_ushort(__float2half_rn(v.x)) | ((u32)__half_as_ushort(__float2half_rn(v.y)) << 16),
            (u32)__half_as_ushort(__float2half_rn(v.z)) | ((u32)__half_as_ushort(__float2half_rn(v.w)) << 16));
    }
}

// -------- tensor-core GEMM (fp16 2-term; 512 threads, 32x32 warp tiles) --------
// CTA 128x128, 16 warps in 4x4 grid. 2 CTAs/SM -> 32 warps/SM.
#define KC      32
#define RSTRIDE 40
#define TILE_E  (128 * RSTRIDE)
#define TILE_B  (TILE_E * 2)
#define STAGE_B (3 * TILE_B)
#define NSTAGE  3
#define SMEM_BYTES (NSTAGE * STAGE_B)

template <int MODE>
__global__ __launch_bounds__(512)
void gemm_mma(const float* __restrict__ bias, float* __restrict__ out) {
    extern __shared__ __half sm[];

    const __half* Ah = MODE ? g_ahi : g_xhi;
    const __half* Al = MODE ? g_alo : g_xlo;
    const __half* Bh = MODE ? g_wphi : g_wqhi;

    const int tid  = threadIdx.x;
    const int warp = tid >> 5;        // 0..15
    const int lane = tid & 31;
    const int g    = lane >> 2;
    const int t4   = lane & 3;
    const int wm   = warp >> 2;       // 0..3 (32 M-rows each)
    const int wn   = warp & 3;        // 0..3 (32 N-cols each)

    const int    o0 = blockIdx.x * 128;
    const size_t m0 = (size_t)blockIdx.y * 128;

    const u32 smem_base = smem_u32(sm);

    // gmem -> smem: 1 x 16B per tile per thread (128 rows x 4 thr-per-row)
    const int row = tid >> 2;                  // 0..127
    const int seg = (tid & 3) * 8;

    const __half* gAh = Ah + (m0 + row) * 256 + seg;
    const __half* gAl = Al + (m0 + row) * 256 + seg;
    const __half* gBh = Bh + (size_t)(o0 + row) * 256 + seg;

    const u32 sb = (u32)(row * RSTRIDE + seg) * 2;

    const int q3 = (lane >> 3) & 1;
    const int q4 = (lane >> 4) & 1;
    const int r8 = lane & 7;
    const u32 offA  = 0 * TILE_B + (u32)(((wm * 32 + q3 * 8 + r8) * RSTRIDE) + q4 * 8) * 2;
    const u32 offB0 = 2 * TILE_B + (u32)(((wn * 32 + 0 * 16 + q4 * 8 + r8) * RSTRIDE) + q3 * 8) * 2;
    const u32 offB1 = 2 * TILE_B + (u32)(((wn * 32 + 1 * 16 + q4 * 8 + r8) * RSTRIDE) + q3 * 8) * 2;

    float acc[2][4][4];
#pragma unroll
    for (int a = 0; a < 2; ++a)
#pragma unroll
        for (int b = 0; b < 4; ++b)
#pragma unroll
            for (int c = 0; c < 4; ++c) acc[a][b][c] = 0.f;

#define ISSUE_STAGE(stg, kb) do {                                      \
        const u32 nx = smem_base + (u32)(stg) * STAGE_B;               \
        CP_ASYNC16(nx + 0 * TILE_B + sb, gAh + (kb));                  \
        CP_ASYNC16(nx + 1 * TILE_B + sb, gAl + (kb));                  \
        CP_ASYNC16(nx + 2 * TILE_B + sb, gBh + (kb));                  \
        CP_COMMIT();                                                   \
    } while (0)

    ISSUE_STAGE(0, 0);
    ISSUE_STAGE(1, KC);

    int cur = 0;
#pragma unroll 1
    for (int kc = 0; kc < 8; ++kc) {
        if (kc < 7) CP_WAITG(1);
        else        CP_WAITG(0);
        __syncthreads();

        if (kc + 2 < 8) {
            int nxt = cur + 2; if (nxt >= 3) nxt -= 3;
            ISSUE_STAGE(nxt, (kc + 2) * KC);
        }

        const u32 stb = smem_base + (u32)cur * STAGE_B;
#pragma unroll
        for (int ks = 0; ks < 2; ++ks) {
            const u32 kso = (u32)(ks * 32);
            u32 bh[4][2];
            LDSM_X4(bh[0][0], bh[0][1], bh[1][0], bh[1][1], stb + offB0 + kso);
            LDSM_X4(bh[2][0], bh[2][1], bh[3][0], bh[3][1], stb + offB1 + kso);
#pragma unroll
            for (int mi = 0; mi < 2; ++mi) {
                const u32 ao = stb + offA + (u32)(mi * 16 * RSTRIDE * 2) + kso;
                u32 ah0, ah1, ah2, ah3, al0, al1, al2, al3;
                LDSM_X4(ah0, ah1, ah2, ah3, ao);
                LDSM_X4(al0, al1, al2, al3, ao + TILE_B);
#pragma unroll
                for (int ni = 0; ni < 4; ++ni) {
                    mma16816(acc[mi][ni], ah0, ah1, ah2, ah3, bh[ni][0], bh[ni][1]);
                    mma16816(acc[mi][ni], al0, al1, al2, al3, bh[ni][0], bh[ni][1]);
                }
            }
        }
        if (++cur == 3) cur = 0;
    }
#undef ISSUE_STAGE

    // ---- epilogue: bias add + store straight from registers ----
#pragma unroll
    for (int mi = 0; mi < 2; ++mi) {
        const int r0 = (int)m0 + wm * 32 + mi * 16 + g;
        const int r1 = r0 + 8;
#pragma unroll
        for (int ni = 0; ni < 4; ++ni) {
            const int c = o0 + wn * 32 + ni * 8 + 2 * t4;
            const float b0 = bias[c], b1 = bias[c + 1];
            float v00 = acc[mi][ni][0] + b0, v01 = acc[mi][ni][1] + b1;
            float v10 = acc[mi][ni][2] + b0, v11 = acc[mi][ni][3] + b1;
            if (MODE == 0) {
                const int which = c >> 8;
                const int head  = (c >> 5) & 7;
                const int d     = c & 31;
#pragma unroll
                for (int rr = 0; rr < 2; ++rr) {
                    const int m = rr ? r1 : r0;
                    const int bwin = m / NTOK;
                    const int n = m - bwin * NTOK;
                    float* dst = g_qkv + (size_t)which * QKV_S +
                        (((size_t)bwin * NH + head) * NTOK + n) * HD + d;
                    *(float2*)dst = rr ? make_float2(v10, v11) : make_float2(v00, v01);
                }
            } else {
                *(float2*)(out + (size_t)r0 * 256 + c) = make_float2(v00, v01);
                *(float2*)(out + (size_t)r1 * 256 + c) = make_float2(v10, v11);
            }
        }
    }
}

// ---------------- fused window attention (R12 proven version) ----------------
__global__ __launch_bounds__(64)
void attn_kernel() {
    __shared__ __align__(16) float pool[3][NTOK][34];
    float (*sq)[34] = pool[0];
    float (*sk)[34] = pool[1];
    float (*sv)[34] = pool[2];
    float (*s)[50]  = (float (*)[50])&pool[0][0][0];

    const int tid = threadIdx.x;
    const int bh = blockIdx.x;
    const int bwin = bh >> 3;
    const int h = bh & 7;

    const size_t base = (size_t)bh * (NTOK * HD);
    const float4* q4 = (const float4*)(g_qkv + base);
    const float4* k4 = (const float4*)(g_qkv + (size_t)QKV_S + base);
    const float4* v4 = (const float4*)(g_qkv + 2ULL * QKV_S + base);

    for (int i = tid; i < NTOK * HD / 4; i += 64) {
        const int r = i >> 3, c = (i & 7) * 4;
        float4 a = q4[i];
        sq[r][c] = a.x; sq[r][c + 1] = a.y; sq[r][c + 2] = a.z; sq[r][c + 3] = a.w;
        float4 b = k4[i];
        sk[r][c] = b.x; sk[r][c + 1] = b.y; sk[r][c + 2] = b.z; sk[r][c + 3] = b.w;
        float4 d = v4[i];
        sv[r][c] = d.x; sv[r][c + 1] = d.y; sv[r][c + 2] = d.z; sv[r][c + 3] = d.w;
    }
    __syncthreads();

    u64 acc[7][7];
    int n0 = 0, m0 = 0;
    if (tid < 49) {
        const int ti = tid / 7, tj = tid - ti * 7;
        n0 = ti * 7; m0 = tj * 7;
#pragma unroll
        for (int r = 0; r < 7; ++r)
#pragma unroll
            for (int cc = 0; cc < 7; ++cc) acc[r][cc] = 0ull;
#pragma unroll
        for (int kk = 0; kk < 16; ++kk) {
            u64 qv[7], kv[7];
#pragma unroll
            for (int r = 0; r < 7; ++r) qv[r] = *(const u64*)&sq[n0 + r][2 * kk];
#pragma unroll
            for (int cc = 0; cc < 7; ++cc) kv[cc] = *(const u64*)&sk[m0 + cc][2 * kk];
#pragma unroll
            for (int r = 0; r < 7; ++r)
#pragma unroll
                for (int cc = 0; cc < 7; ++cc) acc[r][cc] = f2fma(qv[r], kv[cc], acc[r][cc]);
        }
    }
    __syncthreads();

    if (tid < 49) {
        const float scale = 0.17677669529663687f;
        const float* bb = g_bias + h * (NTOK * NTOK);
#pragma unroll
        for (int r = 0; r < 7; ++r)
#pragma unroll
            for (int cc = 0; cc < 7; ++cc) {
                const u64 a = acc[r][cc];
                const float lo = __uint_as_float((u32)(a & 0xffffffffull));
                const float hi = __uint_as_float((u32)(a >> 32));
                s[n0 + r][m0 + cc] = (lo + hi) * scale + bb[(n0 + r) * NTOK + m0 + cc];
            }
    }
    __syncthreads();

    if (tid < 49) {
        float mx = -1e30f;
#pragma unroll
        for (int c = 0; c < NTOK; ++c) mx = fmaxf(mx, s[tid][c]);
        float sum = 0.f;
#pragma unroll
        for (int c = 0; c < NTOK; ++c) {
            float e = __expf(s[tid][c] - mx);
            s[tid][c] = e;
            sum += e;
        }
        const float inv = 1.f / sum;
#pragma unroll
        for (int c = 0; c < NTOK; ++c) s[tid][c] *= inv;
    }
    __syncthreads();

    if (tid < 56) {
        const int ti = tid >> 3, tj = tid & 7;
        const int nn0 = ti * 7, d0 = tj * 4;
        u64 acc2[7][2];
#pragma unroll
        for (int r = 0; r < 7; ++r) { acc2[r][0] = 0ull; acc2[r][1] = 0ull; }
#pragma unroll 7
        for (int m = 0; m < NTOK; ++m) {
            const u64 v0 = *(const u64*)&sv[m][d0];
            const u64 v1 = *(const u64*)&sv[m][d0 + 2];
#pragma unroll
            for (int r = 0; r < 7; ++r) {
                const u64 sd = dup32(s[nn0 + r][m]);
                acc2[r][0] = f2fma(sd, v0, acc2[r][0]);
                acc2[r][1] = f2fma(sd, v1, acc2[r][1]);
            }
        }
#pragma unroll
        for (int r = 0; r < 7; ++r) {
            unsigned short hh[4], ll[4];
#pragma unroll
            for (int cc = 0; cc < 2; ++cc) {
                const u64 a = acc2[r][cc];
                split_h(__uint_as_float((u32)(a & 0xffffffffull)), hh[2 * cc], ll[2 * cc]);
                split_h(__uint_as_float((u32)(a >> 32)), hh[2 * cc + 1], ll[2 * cc + 1]);
            }
            uint2 vh = make_uint2((u32)hh[0] | ((u32)hh[1] << 16), (u32)hh[2] | ((u32)hh[3] << 16));
            uint2 vl = make_uint2((u32)ll[0] | ((u32)ll[1] << 16), (u32)ll[2] | ((u32)ll[3] << 16));
            const size_t off = ((size_t)bwin * NTOK + nn0 + r) * 256 + h * 32 + d0;
            *(uint2*)(g_ahi + off) = vh;
            *(uint2*)(g_alo + off) = vl;
        }
    }
}

// ---------------- launch ----------------
extern "C" void kernel_launch(void* const* d_in, const int* in_sizes, int n_in,
                              void* d_out, int out_size) {
    const float* x      = (const float*)d_in[0];
    const float* qkv_w  = (const float*)d_in[1];
    const float* qkv_b  = (const float*)d_in[2];
    const float* proj_w = (const float*)d_in[3];
    const float* proj_b = (const float*)d_in[4];
    const float* table  = (const float*)d_in[5];
    const int*   rel    = (const int*)d_in[6];
    float* out = (float*)d_out;

    static int smem_set = 0;
    if (!smem_set) {
        cudaFuncSetAttribute(gemm_mma<0>, cudaFuncAttributeMaxDynamicSharedMemorySize, SMEM_BYTES);
        cudaFuncSetAttribute(gemm_mma<1>, cudaFuncAttributeMaxDynamicSharedMemorySize, SMEM_BYTES);
        smem_set = 1;
    }

    bias_kernel<<<(NH * NTOK * NTOK + 255) / 256, 256>>>(table, rel);
    conv_x<<<(int)(((size_t)MTOT * DIM / 4 + 255) / 256), 256>>>(x);
    conv_w<<<((768 + 256) * 256 / 4 + 255) / 256, 256>>>(qkv_w, proj_w);
    gemm_mma<0><<<dim3(6, MTOT / 128), 512, SMEM_BYTES>>>(qkv_b, nullptr);
    attn_kernel<<<BWIN * NH, 64>>>();
    gemm_mma<1><<<dim3(2, MTOT / 128), 512, SMEM_BYTES>>>(proj_b, out);
}

// round 15
// speedup vs baseline: 1.1279x; 1.0227x over previous
#include <cuda_runtime.h>
#include <cuda_fp16.h>
#include <cstdint>

#define BWIN 4096
#define NTOK 49
#define DIM  256
#define NH   8
#define HD   32
#define MTOT (BWIN * NTOK)            /* 200704 */
#define QKV_S (BWIN * NH * NTOK * HD) /* 51380224 */

typedef unsigned long long u64;
typedef unsigned int u32;

// ---------------- device scratch (allocation-free) ----------------
__device__ float g_qkv[3ULL * QKV_S];                       // fp32 [3][B][H][N][hd]
__device__ float g_bias[NH * NTOK * NTOK];                  // [H][N][N]
__device__ __align__(16) __half g_xhi[(size_t)MTOT * DIM];
__device__ __align__(16) __half g_xlo[(size_t)MTOT * DIM];
__device__ __align__(16) __half g_ahi[(size_t)MTOT * DIM];
__device__ __align__(16) __half g_alo[(size_t)MTOT * DIM];
__device__ __align__(16) __half g_wqhi[768 * 256];
__device__ __align__(16) __half g_wphi[256 * 256];

// ---------------- helpers ----------------
__device__ __forceinline__ u64 f2fma(u64 a, u64 b, u64 c) {
    u64 d;
    asm("fma.rn.f32x2 %0, %1, %2, %3;" : "=l"(d) : "l"(a), "l"(b), "l"(c));
    return d;
}
__device__ __forceinline__ u64 dup32(float x) {
    u64 d;
    asm("mov.b64 %0, {%1, %1};" : "=l"(d) : "r"(__float_as_uint(x)));
    return d;
}
__device__ __forceinline__ void split_h(float x, unsigned short& h, unsigned short& l) {
    __half hb = __float2half_rn(x);
    float r = x - __half2float(hb);
    __half lb = __float2half_rn(r);
    h = __half_as_ushort(hb);
    l = __half_as_ushort(lb);
}
__device__ __forceinline__ u32 smem_u32(const void* p) {
    u32 a;
    asm("{ .reg .u64 t; cvta.to.shared.u64 t, %1; cvt.u32.u64 %0, t; }" : "=r"(a) : "l"(p));
    return a;
}

__device__ __forceinline__ void mma16816(float* d, u32 a0, u32 a1, u32 a2, u32 a3,
                                         u32 b0, u32 b1) {
    asm volatile(
        "mma.sync.aligned.m16n8k16.row.col.f32.f16.f16.f32 "
        "{%0,%1,%2,%3}, {%4,%5,%6,%7}, {%8,%9}, {%0,%1,%2,%3};"
        : "+f"(d[0]), "+f"(d[1]), "+f"(d[2]), "+f"(d[3])
        : "r"(a0), "r"(a1), "r"(a2), "r"(a3), "r"(b0), "r"(b1));
}

#define LDSM_X4(r0, r1, r2, r3, addr) \
    asm volatile("ldmatrix.sync.aligned.m8n8.x4.shared.b16 {%0,%1,%2,%3}, [%4];" \
        : "=r"(r0), "=r"(r1), "=r"(r2), "=r"(r3) : "r"(addr))

#define CP_ASYNC16(s, g) \
    asm volatile("cp.async.cg.shared.global [%0], [%1], 16;" :: "r"(s), "l"(g))
#define CP_COMMIT() asm volatile("cp.async.commit_group;" ::: "memory")
#define CP_WAITG(n) asm volatile("cp.async.wait_group %0;" :: "n"(n) : "memory")

// ---------------- fused preprocessing: conv_x + conv_w + bias gather ----------------
__global__ void pre_kernel(const float* __restrict__ x,
                           const float* __restrict__ wq,
                           const float* __restrict__ wp,
                           const float* __restrict__ table,
                           const int* __restrict__ rel) {
    const size_t idx = (size_t)blockIdx.x * 256 + threadIdx.x;

    // conv_x: hi/lo split of x, 4 floats per thread
    if (idx < (size_t)MTOT * DIM / 4) {
        float4 v = ((const float4*)x)[idx];
        unsigned short h0, h1, h2, h3, l0, l1, l2, l3;
        split_h(v.x, h0, l0); split_h(v.y, h1, l1);
        split_h(v.z, h2, l2); split_h(v.w, h3, l3);
        ((uint2*)g_xhi)[idx] = make_uint2((u32)h0 | ((u32)h1 << 16), (u32)h2 | ((u32)h3 << 16));
        ((uint2*)g_xlo)[idx] = make_uint2((u32)l0 | ((u32)l1 << 16), (u32)l2 | ((u32)l3 << 16));
    }
    // conv_w: hi-only of both weight matrices
    const int nq4 = 768 * 256 / 4;
    const int np4 = 256 * 256 / 4;
    if (idx < (size_t)(nq4 + np4)) {
        if (idx < (size_t)nq4) {
            float4 v = ((const float4*)wq)[idx];
            ((uint2*)g_wqhi)[idx] = make_uint2(
                (u32)__half_as_ushort(__float2half_rn(v.x)) | ((u32)__half_as_ushort(__float2half_rn(v.y)) << 16),
                (u32)__half_as_ushort(__float2half_rn(v.z)) | ((u32)__half_as_ushort(__float2half_rn(v.w)) << 16));
        } else {
            int j = (int)idx - nq4;
            float4 v = ((const float4*)wp)[j];
            ((uint2*)g_wphi)[j] = make_uint2(
                (u32)__half_as_ushort(__float2half_rn(v.x)) | ((u32)__half_as_ushort(__float2half_rn(v.y)) << 16),
                (u32)__half_as_ushort(__float2half_rn(v.z)) | ((u32)__half_as_ushort(__float2half_rn(v.w)) << 16));
        }
    }
    // bias gather
    if (idx < (size_t)(NH * NTOK * NTOK)) {
        int h = (int)idx / (NTOK * NTOK);
        int nm = (int)idx - h * (NTOK * NTOK);
        g_bias[idx] = table[rel[nm] * NH + h];
    }
}

// -------- tensor-core GEMM (fp16 2-term; 512 threads, 32x32 warp tiles) --------
#define KC      32
#define RSTRIDE 40
#define TILE_E  (128 * RSTRIDE)
#define TILE_B  (TILE_E * 2)
#define STAGE_B (3 * TILE_B)
#define NSTAGE  3
#define SMEM_BYTES (NSTAGE * STAGE_B)

template <int MODE>
__global__ __launch_bounds__(512)
void gemm_mma(const float* __restrict__ bias, float* __restrict__ out) {
    extern __shared__ __half sm[];

    const __half* Ah = MODE ? g_ahi : g_xhi;
    const __half* Al = MODE ? g_alo : g_xlo;
    const __half* Bh = MODE ? g_wphi : g_wqhi;

    const int tid  = threadIdx.x;
    const int warp = tid >> 5;
    const int lane = tid & 31;
    const int g    = lane >> 2;
    const int t4   = lane & 3;
    const int wm   = warp >> 2;
    const int wn   = warp & 3;

    const int    o0 = blockIdx.x * 128;
    const size_t m0 = (size_t)blockIdx.y * 128;

    const u32 smem_base = smem_u32(sm);

    const int row = tid >> 2;
    const int seg = (tid & 3) * 8;

    const __half* gAh = Ah + (m0 + row) * 256 + seg;
    const __half* gAl = Al + (m0 + row) * 256 + seg;
    const __half* gBh = Bh + (size_t)(o0 + row) * 256 + seg;

    const u32 sb = (u32)(row * RSTRIDE + seg) * 2;

    const int q3 = (lane >> 3) & 1;
    const int q4 = (lane >> 4) & 1;
    const int r8 = lane & 7;
    const u32 offA  = 0 * TILE_B + (u32)(((wm * 32 + q3 * 8 + r8) * RSTRIDE) + q4 * 8) * 2;
    const u32 offB0 = 2 * TILE_B + (u32)(((wn * 32 + 0 * 16 + q4 * 8 + r8) * RSTRIDE) + q3 * 8) * 2;
    const u32 offB1 = 2 * TILE_B + (u32)(((wn * 32 + 1 * 16 + q4 * 8 + r8) * RSTRIDE) + q3 * 8) * 2;

    float acc[2][4][4];
#pragma unroll
    for (int a = 0; a < 2; ++a)
#pragma unroll
        for (int b = 0; b < 4; ++b)
#pragma unroll
            for (int c = 0; c < 4; ++c) acc[a][b][c] = 0.f;

#define ISSUE_STAGE(stg, kb) do {                                      \
        const u32 nx = smem_base + (u32)(stg) * STAGE_B;               \
        CP_ASYNC16(nx + 0 * TILE_B + sb, gAh + (kb));                  \
        CP_ASYNC16(nx + 1 * TILE_B + sb, gAl + (kb));                  \
        CP_ASYNC16(nx + 2 * TILE_B + sb, gBh + (kb));                  \
        CP_COMMIT();                                                   \
    } while (0)

    ISSUE_STAGE(0, 0);
    ISSUE_STAGE(1, KC);

    int cur = 0;
#pragma unroll 1
    for (int kc = 0; kc < 8; ++kc) {
        if (kc < 7) CP_WAITG(1);
        else        CP_WAITG(0);
        __syncthreads();

        if (kc + 2 < 8) {
            int nxt = cur + 2; if (nxt >= 3) nxt -= 3;
            ISSUE_STAGE(nxt, (kc + 2) * KC);
        }

        const u32 stb = smem_base + (u32)cur * STAGE_B;
#pragma unroll
        for (int ks = 0; ks < 2; ++ks) {
            const u32 kso = (u32)(ks * 32);
            u32 bh[4][2];
            LDSM_X4(bh[0][0], bh[0][1], bh[1][0], bh[1][1], stb + offB0 + kso);
            LDSM_X4(bh[2][0], bh[2][1], bh[3][0], bh[3][1], stb + offB1 + kso);
#pragma unroll
            for (int mi = 0; mi < 2; ++mi) {
                const u32 ao = stb + offA + (u32)(mi * 16 * RSTRIDE * 2) + kso;
                u32 ah0, ah1, ah2, ah3, al0, al1, al2, al3;
                LDSM_X4(ah0, ah1, ah2, ah3, ao);
                LDSM_X4(al0, al1, al2, al3, ao + TILE_B);
#pragma unroll
                for (int ni = 0; ni < 4; ++ni) {
                    mma16816(acc[mi][ni], ah0, ah1, ah2, ah3, bh[ni][0], bh[ni][1]);
                    mma16816(acc[mi][ni], al0, al1, al2, al3, bh[ni][0], bh[ni][1]);
                }
            }
        }
        if (++cur == 3) cur = 0;
    }
#undef ISSUE_STAGE

    // ---- epilogue: bias add + store straight from registers ----
#pragma unroll
    for (int mi = 0; mi < 2; ++mi) {
        const int r0 = (int)m0 + wm * 32 + mi * 16 + g;
        const int r1 = r0 + 8;
#pragma unroll
        for (int ni = 0; ni < 4; ++ni) {
            const int c = o0 + wn * 32 + ni * 8 + 2 * t4;
            const float b0 = bias[c], b1 = bias[c + 1];
            float v00 = acc[mi][ni][0] + b0, v01 = acc[mi][ni][1] + b1;
            float v10 = acc[mi][ni][2] + b0, v11 = acc[mi][ni][3] + b1;
            if (MODE == 0) {
                const int which = c >> 8;
                const int head  = (c >> 5) & 7;
                const int d     = c & 31;
#pragma unroll
                for (int rr = 0; rr < 2; ++rr) {
                    const int m = rr ? r1 : r0;
                    const int bwin = m / NTOK;
                    const int n = m - bwin * NTOK;
                    float* dst = g_qkv + (size_t)which * QKV_S +
                        (((size_t)bwin * NH + head) * NTOK + n) * HD + d;
                    *(float2*)dst = rr ? make_float2(v10, v11) : make_float2(v00, v01);
                }
            } else {
                *(float2*)(out + (size_t)r0 * 256 + c) = make_float2(v00, v01);
                *(float2*)(out + (size_t)r1 * 256 + c) = make_float2(v10, v11);
            }
        }
    }
}

// ---------------- fused window attention (R12 core + inv-fold + float4 PV) ----------------
// pool rows padded to 52 so PV may read sv rows 49..51 (zeroed).
// s[49][52] (16B-aligned rows) aliases pool[0..1]; sinv holds 1/rowsum.
__global__ __launch_bounds__(64)
void attn_kernel() {
    __shared__ __align__(16) float pool[3][52][34];
    __shared__ float sinv[NTOK];
    float (*sq)[34] = pool[0];
    float (*sk)[34] = pool[1];
    float (*sv)[34] = pool[2];
    float (*s)[52]  = (float (*)[52])&pool[0][0][0];   // 49*52=2548 <= 2*52*34=3536

    const int tid = threadIdx.x;
    const int bh = blockIdx.x;
    const int bwin = bh >> 3;
    const int h = bh & 7;

    // zero sv pad rows 49..51 (PV tail guard)
    for (int i = tid; i < 3 * 34; i += 64) sv[49 + i / 34][i % 34] = 0.f;

    const size_t base = (size_t)bh * (NTOK * HD);
    const float4* q4 = (const float4*)(g_qkv + base);
    const float4* k4 = (const float4*)(g_qkv + (size_t)QKV_S + base);
    const float4* v4 = (const float4*)(g_qkv + 2ULL * QKV_S + base);

    for (int i = tid; i < NTOK * HD / 4; i += 64) {
        const int r = i >> 3, c = (i & 7) * 4;
        float4 a = q4[i];
        sq[r][c] = a.x; sq[r][c + 1] = a.y; sq[r][c + 2] = a.z; sq[r][c + 3] = a.w;
        float4 b = k4[i];
        sk[r][c] = b.x; sk[r][c + 1] = b.y; sk[r][c + 2] = b.z; sk[r][c + 3] = b.w;
        float4 d = v4[i];
        sv[r][c] = d.x; sv[r][c + 1] = d.y; sv[r][c + 2] = d.z; sv[r][c + 3] = d.w;
    }
    __syncthreads();

    // QK^T into registers (reads sq/sk only)
    u64 acc[7][7];
    int n0 = 0, m0 = 0;
    if (tid < 49) {
        const int ti = tid / 7, tj = tid - ti * 7;
        n0 = ti * 7; m0 = tj * 7;
#pragma unroll
        for (int r = 0; r < 7; ++r)
#pragma unroll
            for (int cc = 0; cc < 7; ++cc) acc[r][cc] = 0ull;
#pragma unroll
        for (int kk = 0; kk < 16; ++kk) {
            u64 qv[7], kv[7];
#pragma unroll
            for (int r = 0; r < 7; ++r) qv[r] = *(const u64*)&sq[n0 + r][2 * kk];
#pragma unroll
            for (int cc = 0; cc < 7; ++cc) kv[cc] = *(const u64*)&sk[m0 + cc][2 * kk];
#pragma unroll
            for (int r = 0; r < 7; ++r)
#pragma unroll
                for (int cc = 0; cc < 7; ++cc) acc[r][cc] = f2fma(qv[r], kv[cc], acc[r][cc]);
        }
    }
    __syncthreads();   // sq/sk reads done before s (aliased) is written

    if (tid < 49) {
        const float scale = 0.17677669529663687f;
        const float* bb = g_bias + h * (NTOK * NTOK);
#pragma unroll
        for (int r = 0; r < 7; ++r)
#pragma unroll
            for (int cc = 0; cc < 7; ++cc) {
                const u64 a = acc[r][cc];
                const float lo = __uint_as_float((u32)(a & 0xffffffffull));
                const float hi = __uint_as_float((u32)(a >> 32));
                s[n0 + r][m0 + cc] = (lo + hi) * scale + bb[(n0 + r) * NTOK + m0 + cc];
            }
    }
    __syncthreads();

    // softmax: exp + sum; store UNSCALED e, record 1/sum
    if (tid < 49) {
        float mx = -1e30f;
#pragma unroll
        for (int c = 0; c < NTOK; ++c) mx = fmaxf(mx, s[tid][c]);
        float sum = 0.f;
#pragma unroll
        for (int c = 0; c < NTOK; ++c) {
            float e = __expf(s[tid][c] - mx);
            s[tid][c] = e;
            sum += e;
        }
        sinv[tid] = 1.f / sum;
    }
    __syncthreads();

    // P @ V: 56 threads, 7(n) x 4(d) tiles; s loaded as float4 (12 groups + tail)
    if (tid < 56) {
        const int ti = tid >> 3, tj = tid & 7;
        const int nn0 = ti * 7, d0 = tj * 4;
        u64 acc2[7][2];
#pragma unroll
        for (int r = 0; r < 7; ++r) { acc2[r][0] = 0ull; acc2[r][1] = 0ull; }

#pragma unroll 3
        for (int mg = 0; mg < 12; ++mg) {
            const int m = mg * 4;
            float4 s4[7];
#pragma unroll
            for (int r = 0; r < 7; ++r) s4[r] = *(const float4*)&s[nn0 + r][m];
#pragma unroll
            for (int j = 0; j < 4; ++j) {
                const u64 v0 = *(const u64*)&sv[m + j][d0];
                const u64 v1 = *(const u64*)&sv[m + j][d0 + 2];
#pragma unroll
                for (int r = 0; r < 7; ++r) {
                    const float sj = (j == 0) ? s4[r].x : (j == 1) ? s4[r].y
                                   : (j == 2) ? s4[r].z : s4[r].w;
                    const u64 sd = dup32(sj);
                    acc2[r][0] = f2fma(sd, v0, acc2[r][0]);
                    acc2[r][1] = f2fma(sd, v1, acc2[r][1]);
                }
            }
        }
        {   // tail m = 48
            const u64 v0 = *(const u64*)&sv[48][d0];
            const u64 v1 = *(const u64*)&sv[48][d0 + 2];
#pragma unroll
            for (int r = 0; r < 7; ++r) {
                const u64 sd = dup32(s[nn0 + r][48]);
                acc2[r][0] = f2fma(sd, v0, acc2[r][0]);
                acc2[r][1] = f2fma(sd, v1, acc2[r][1]);
            }
        }

#pragma unroll
        for (int r = 0; r < 7; ++r) {
            const float inv = sinv[nn0 + r];
            unsigned short hh[4], ll[4];
#pragma unroll
            for (int cc = 0; cc < 2; ++cc) {
                const u64 a = acc2[r][cc];
                split_h(__uint_as_float((u32)(a & 0xffffffffull)) * inv, hh[2 * cc], ll[2 * cc]);
                split_h(__uint_as_float((u32)(a >> 32)) * inv, hh[2 * cc + 1], ll[2 * cc + 1]);
            }
            uint2 vh = make_uint2((u32)hh[0] | ((u32)hh[1] << 16), (u32)hh[2] | ((u32)hh[3] << 16));
            uint2 vl = make_uint2((u32)ll[0] | ((u32)ll[1] << 16), (u32)ll[2] | ((u32)ll[3] << 16));
            const size_t off = ((size_t)bwin * NTOK + nn0 + r) * 256 + h * 32 + d0;
            *(uint2*)(g_ahi + off) = vh;
            *(uint2*)(g_alo + off) = vl;
        }
    }
}

// ---------------- launch ----------------
extern "C" void kernel_launch(void* const* d_in, const int* in_sizes, int n_in,
                              void* d_out, int out_size) {
    const float* x      = (const float*)d_in[0];
    const float* qkv_w  = (const float*)d_in[1];
    const float* qkv_b  = (const float*)d_in[2];
    const float* proj_w = (const float*)d_in[3];
    const float* proj_b = (const float*)d_in[4];
    const float* table  = (const float*)d_in[5];
    const int*   rel    = (const int*)d_in[6];
    float* out = (float*)d_out;

    static int smem_set = 0;
    if (!smem_set) {
        cudaFuncSetAttribute(gemm_mma<0>, cudaFuncAttributeMaxDynamicSharedMemorySize, SMEM_BYTES);
        cudaFuncSetAttribute(gemm_mma<1>, cudaFuncAttributeMaxDynamicSharedMemorySize, SMEM_BYTES);
        smem_set = 1;
    }

    pre_kernel<<<(int)(((size_t)MTOT * DIM / 4 + 255) / 256), 256>>>(x, qkv_w, proj_w, table, rel);
    gemm_mma<0><<<dim3(6, MTOT / 128), 512, SMEM_BYTES>>>(qkv_b, nullptr);
    attn_kernel<<<BWIN * NH, 64>>>();
    gemm_mma<1><<<dim3(2, MTOT / 128), 512, SMEM_BYTES>>>(proj_b, out);
}

// round 16
// speedup vs baseline: 1.3137x; 1.1647x over previous
#include <cuda_runtime.h>
#include <cuda_fp16.h>
#include <cstdint>

#define BWIN 4096
#define NTOK 49
#define DIM  256
#define NH   8
#define HD   32
#define MTOT (BWIN * NTOK)            /* 200704 */
#define QKV_S (BWIN * NH * NTOK * HD) /* 51380224 */

typedef unsigned long long u64;
typedef unsigned int u32;

// ---------------- device scratch (allocation-free) ----------------
__device__ float g_qkv[3ULL * QKV_S];                       // fp32 [3][B][H][N][hd]
__device__ float g_bias[NH * NTOK * NTOK];                  // [H][N][N]
__device__ __align__(16) __half g_xhi[(size_t)MTOT * DIM];
__device__ __align__(16) __half g_ahi[(size_t)MTOT * DIM];
__device__ __align__(16) __half g_alo[(size_t)MTOT * DIM];
__device__ __align__(16) __half g_wqhi[768 * 256];
__device__ __align__(16) __half g_wphi[256 * 256];

// ---------------- helpers ----------------
__device__ __forceinline__ u64 f2fma(u64 a, u64 b, u64 c) {
    u64 d;
    asm("fma.rn.f32x2 %0, %1, %2, %3;" : "=l"(d) : "l"(a), "l"(b), "l"(c));
    return d;
}
__device__ __forceinline__ u64 dup32(float x) {
    u64 d;
    asm("mov.b64 %0, {%1, %1};" : "=l"(d) : "r"(__float_as_uint(x)));
    return d;
}
__device__ __forceinline__ void split_h(float x, unsigned short& h, unsigned short& l) {
    __half hb = __float2half_rn(x);
    float r = x - __half2float(hb);
    __half lb = __float2half_rn(r);
    h = __half_as_ushort(hb);
    l = __half_as_ushort(lb);
}
__device__ __forceinline__ u32 smem_u32(const void* p) {
    u32 a;
    asm("{ .reg .u64 t; cvta.to.shared.u64 t, %1; cvt.u32.u64 %0, t; }" : "=r"(a) : "l"(p));
    return a;
}

__device__ __forceinline__ void mma16816(float* d, u32 a0, u32 a1, u32 a2, u32 a3,
                                         u32 b0, u32 b1) {
    asm volatile(
        "mma.sync.aligned.m16n8k16.row.col.f32.f16.f16.f32 "
        "{%0,%1,%2,%3}, {%4,%5,%6,%7}, {%8,%9}, {%0,%1,%2,%3};"
        : "+f"(d[0]), "+f"(d[1]), "+f"(d[2]), "+f"(d[3])
        : "r"(a0), "r"(a1), "r"(a2), "r"(a3), "r"(b0), "r"(b1));
}

#define LDSM_X4(r0, r1, r2, r3, addr) \
    asm volatile("ldmatrix.sync.aligned.m8n8.x4.shared.b16 {%0,%1,%2,%3}, [%4];" \
        : "=r"(r0), "=r"(r1), "=r"(r2), "=r"(r3) : "r"(addr))

#define CP_ASYNC16(s, g) \
    asm volatile("cp.async.cg.shared.global [%0], [%1], 16;" :: "r"(s), "l"(g))
#define CP_COMMIT() asm volatile("cp.async.commit_group;" ::: "memory")
#define CP_WAITG(n) asm volatile("cp.async.wait_group %0;" :: "n"(n) : "memory")

// ---------------- fused preprocessing: conv_x(hi) + conv_w + bias gather ----------------
__global__ void pre_kernel(const float* __restrict__ x,
                           const float* __restrict__ wq,
                           const float* __restrict__ wp,
                           const float* __restrict__ table,
                           const int* __restrict__ rel) {
    const size_t idx = (size_t)blockIdx.x * 256 + threadIdx.x;

    if (idx < (size_t)MTOT * DIM / 4) {
        float4 v = ((const float4*)x)[idx];
        ((uint2*)g_xhi)[idx] = make_uint2(
            (u32)__half_as_ushort(__float2half_rn(v.x)) | ((u32)__half_as_ushort(__float2half_rn(v.y)) << 16),
            (u32)__half_as_ushort(__float2half_rn(v.z)) | ((u32)__half_as_ushort(__float2half_rn(v.w)) << 16));
    }
    const int nq4 = 768 * 256 / 4;
    const int np4 = 256 * 256 / 4;
    if (idx < (size_t)(nq4 + np4)) {
        if (idx < (size_t)nq4) {
            float4 v = ((const float4*)wq)[idx];
            ((uint2*)g_wqhi)[idx] = make_uint2(
                (u32)__half_as_ushort(__float2half_rn(v.x)) | ((u32)__half_as_ushort(__float2half_rn(v.y)) << 16),
                (u32)__half_as_ushort(__float2half_rn(v.z)) | ((u32)__half_as_ushort(__float2half_rn(v.w)) << 16));
        } else {
            int j = (int)idx - nq4;
            float4 v = ((const float4*)wp)[j];
            ((uint2*)g_wphi)[j] = make_uint2(
                (u32)__half_as_ushort(__float2half_rn(v.x)) | ((u32)__half_as_ushort(__float2half_rn(v.y)) << 16),
                (u32)__half_as_ushort(__float2half_rn(v.z)) | ((u32)__half_as_ushort(__float2half_rn(v.w)) << 16));
        }
    }
    if (idx < (size_t)(NH * NTOK * NTOK)) {
        int h = (int)idx / (NTOK * NTOK);
        int nm = (int)idx - h * (NTOK * NTOK);
        g_bias[idx] = table[rel[nm] * NH + h];
    }
}

// -------- tensor-core GEMM (512 threads, 32x32 warp tiles) --------
// NTERMS=1: D = Ah*Bh             (tiles Ah, Bh;     stage 20 KB)
// NTERMS=2: D = Ah*Bh + Al*Bh     (tiles Ah, Al, Bh; stage 30 KB)
#define KC      32
#define RSTRIDE 40
#define TILE_E  (128 * RSTRIDE)
#define TILE_B  (TILE_E * 2)
#define NSTAGE  3

template <int MODE, int NTERMS>
__global__ __launch_bounds__(512)
void gemm_mma(const float* __restrict__ bias, float* __restrict__ out) {
    constexpr int NTILES  = NTERMS + 1;
    constexpr int STAGE_B = NTILES * TILE_B;
    extern __shared__ __half sm[];

    const __half* Ah = MODE ? g_ahi : g_xhi;
    const __half* Al = MODE ? g_alo : g_xhi;   // unused when NTERMS==1
    const __half* Bh = MODE ? g_wphi : g_wqhi;

    const int tid  = threadIdx.x;
    const int warp = tid >> 5;
    const int lane = tid & 31;
    const int g    = lane >> 2;
    const int t4   = lane & 3;
    const int wm   = warp >> 2;
    const int wn   = warp & 3;

    const int    o0 = blockIdx.x * 128;
    const size_t m0 = (size_t)blockIdx.y * 128;

    const u32 smem_base = smem_u32(sm);

    const int row = tid >> 2;
    const int seg = (tid & 3) * 8;

    const __half* gAh = Ah + (m0 + row) * 256 + seg;
    const __half* gAl = Al + (m0 + row) * 256 + seg;
    const __half* gBh = Bh + (size_t)(o0 + row) * 256 + seg;

    const u32 sb = (u32)(row * RSTRIDE + seg) * 2;

    const int q3 = (lane >> 3) & 1;
    const int q4 = (lane >> 4) & 1;
    const int r8 = lane & 7;
    const u32 offA  = 0 * TILE_B + (u32)(((wm * 32 + q3 * 8 + r8) * RSTRIDE) + q4 * 8) * 2;
    const u32 offB0 = NTERMS * TILE_B + (u32)(((wn * 32 + 0 * 16 + q4 * 8 + r8) * RSTRIDE) + q3 * 8) * 2;
    const u32 offB1 = NTERMS * TILE_B + (u32)(((wn * 32 + 1 * 16 + q4 * 8 + r8) * RSTRIDE) + q3 * 8) * 2;

    float acc[2][4][4];
#pragma unroll
    for (int a = 0; a < 2; ++a)
#pragma unroll
        for (int b = 0; b < 4; ++b)
#pragma unroll
            for (int c = 0; c < 4; ++c) acc[a][b][c] = 0.f;

#define ISSUE_STAGE(stg, kb) do {                                      \
        const u32 nx = smem_base + (u32)(stg) * STAGE_B;               \
        CP_ASYNC16(nx + 0 * TILE_B + sb, gAh + (kb));                  \
        if (NTERMS == 2) CP_ASYNC16(nx + 1 * TILE_B + sb, gAl + (kb)); \
        CP_ASYNC16(nx + NTERMS * TILE_B + sb, gBh + (kb));             \
        CP_COMMIT();                                                   \
    } while (0)

    ISSUE_STAGE(0, 0);
    ISSUE_STAGE(1, KC);

    int cur = 0;
#pragma unroll 1
    for (int kc = 0; kc < 8; ++kc) {
        if (kc < 7) CP_WAITG(1);
        else        CP_WAITG(0);
        __syncthreads();

        if (kc + 2 < 8) {
            int nxt = cur + 2; if (nxt >= 3) nxt -= 3;
            ISSUE_STAGE(nxt, (kc + 2) * KC);
        }

        const u32 stb = smem_base + (u32)cur * STAGE_B;
#pragma unroll
        for (int ks = 0; ks < 2; ++ks) {
            const u32 kso = (u32)(ks * 32);
            u32 bh[4][2];
            LDSM_X4(bh[0][0], bh[0][1], bh[1][0], bh[1][1], stb + offB0 + kso);
            LDSM_X4(bh[2][0], bh[2][1], bh[3][0], bh[3][1], stb + offB1 + kso);
#pragma unroll
            for (int mi = 0; mi < 2; ++mi) {
                const u32 ao = stb + offA + (u32)(mi * 16 * RSTRIDE * 2) + kso;
                u32 ah0, ah1, ah2, ah3;
                LDSM_X4(ah0, ah1, ah2, ah3, ao);
                u32 al0, al1, al2, al3;
                if (NTERMS == 2) LDSM_X4(al0, al1, al2, al3, ao + TILE_B);
#pragma unroll
                for (int ni = 0; ni < 4; ++ni) {
                    mma16816(acc[mi][ni], ah0, ah1, ah2, ah3, bh[ni][0], bh[ni][1]);
                    if (NTERMS == 2)
                        mma16816(acc[mi][ni], al0, al1, al2, al3, bh[ni][0], bh[ni][1]);
                }
            }
        }
        if (++cur == 3) cur = 0;
    }
#undef ISSUE_STAGE

    // ---- epilogue: bias add + store straight from registers ----
#pragma unroll
    for (int mi = 0; mi < 2; ++mi) {
        const int r0 = (int)m0 + wm * 32 + mi * 16 + g;
        const int r1 = r0 + 8;
#pragma unroll
        for (int ni = 0; ni < 4; ++ni) {
            const int c = o0 + wn * 32 + ni * 8 + 2 * t4;
            const float b0 = bias[c], b1 = bias[c + 1];
            float v00 = acc[mi][ni][0] + b0, v01 = acc[mi][ni][1] + b1;
            float v10 = acc[mi][ni][2] + b0, v11 = acc[mi][ni][3] + b1;
            if (MODE == 0) {
                const int which = c >> 8;
                const int head  = (c >> 5) & 7;
                const int d     = c & 31;
#pragma unroll
                for (int rr = 0; rr < 2; ++rr) {
                    const int m = rr ? r1 : r0;
                    const int bwin = m / NTOK;
                    const int n = m - bwin * NTOK;
                    float* dst = g_qkv + (size_t)which * QKV_S +
                        (((size_t)bwin * NH + head) * NTOK + n) * HD + d;
                    *(float2*)dst = rr ? make_float2(v10, v11) : make_float2(v00, v01);
                }
            } else {
                *(float2*)(out + (size_t)r0 * 256 + c) = make_float2(v00, v01);
                *(float2*)(out + (size_t)r1 * 256 + c) = make_float2(v10, v11);
            }
        }
    }
}

// ---------------- fused window attention (R15 proven version) ----------------
__global__ __launch_bounds__(64)
void attn_kernel() {
    __shared__ __align__(16) float pool[3][52][34];
    __shared__ float sinv[NTOK];
    float (*sq)[34] = pool[0];
    float (*sk)[34] = pool[1];
    float (*sv)[34] = pool[2];
    float (*s)[52]  = (float (*)[52])&pool[0][0][0];

    const int tid = threadIdx.x;
    const int bh = blockIdx.x;
    const int bwin = bh >> 3;
    const int h = bh & 7;

    for (int i = tid; i < 3 * 34; i += 64) sv[49 + i / 34][i % 34] = 0.f;

    const size_t base = (size_t)bh * (NTOK * HD);
    const float4* q4 = (const float4*)(g_qkv + base);
    const float4* k4 = (const float4*)(g_qkv + (size_t)QKV_S + base);
    const float4* v4 = (const float4*)(g_qkv + 2ULL * QKV_S + base);

    for (int i = tid; i < NTOK * HD / 4; i += 64) {
        const int r = i >> 3, c = (i & 7) * 4;
        float4 a = q4[i];
        sq[r][c] = a.x; sq[r][c + 1] = a.y; sq[r][c + 2] = a.z; sq[r][c + 3] = a.w;
        float4 b = k4[i];
        sk[r][c] = b.x; sk[r][c + 1] = b.y; sk[r][c + 2] = b.z; sk[r][c + 3] = b.w;
        float4 d = v4[i];
        sv[r][c] = d.x; sv[r][c + 1] = d.y; sv[r][c + 2] = d.z; sv[r][c + 3] = d.w;
    }
    __syncthreads();

    u64 acc[7][7];
    int n0 = 0, m0 = 0;
    if (tid < 49) {
        const int ti = tid / 7, tj = tid - ti * 7;
        n0 = ti * 7; m0 = tj * 7;
#pragma unroll
        for (int r = 0; r < 7; ++r)
#pragma unroll
            for (int cc = 0; cc < 7; ++cc) acc[r][cc] = 0ull;
#pragma unroll
        for (int kk = 0; kk < 16; ++kk) {
            u64 qv[7], kv[7];
#pragma unroll
            for (int r = 0; r < 7; ++r) qv[r] = *(const u64*)&sq[n0 + r][2 * kk];
#pragma unroll
            for (int cc = 0; cc < 7; ++cc) kv[cc] = *(const u64*)&sk[m0 + cc][2 * kk];
#pragma unroll
            for (int r = 0; r < 7; ++r)
#pragma unroll
                for (int cc = 0; cc < 7; ++cc) acc[r][cc] = f2fma(qv[r], kv[cc], acc[r][cc]);
        }
    }
    __syncthreads();

    if (tid < 49) {
        const float scale = 0.17677669529663687f;
        const float* bb = g_bias + h * (NTOK * NTOK);
#pragma unroll
        for (int r = 0; r < 7; ++r)
#pragma unroll
            for (int cc = 0; cc < 7; ++cc) {
                const u64 a = acc[r][cc];
                const float lo = __uint_as_float((u32)(a & 0xffffffffull));
                const float hi = __uint_as_float((u32)(a >> 32));
                s[n0 + r][m0 + cc] = (lo + hi) * scale + bb[(n0 + r) * NTOK + m0 + cc];
            }
    }
    __syncthreads();

    if (tid < 49) {
        float mx = -1e30f;
#pragma unroll
        for (int c = 0; c < NTOK; ++c) mx = fmaxf(mx, s[tid][c]);
        float sum = 0.f;
#pragma unroll
        for (int c = 0; c < NTOK; ++c) {
            float e = __expf(s[tid][c] - mx);
            s[tid][c] = e;
            sum += e;
        }
        sinv[tid] = 1.f / sum;
    }
    __syncthreads();

    if (tid < 56) {
        const int ti = tid >> 3, tj = tid & 7;
        const int nn0 = ti * 7, d0 = tj * 4;
        u64 acc2[7][2];
#pragma unroll
        for (int r = 0; r < 7; ++r) { acc2[r][0] = 0ull; acc2[r][1] = 0ull; }

#pragma unroll 3
        for (int mg = 0; mg < 12; ++mg) {
            const int m = mg * 4;
            float4 s4[7];
#pragma unroll
            for (int r = 0; r < 7; ++r) s4[r] = *(const float4*)&s[nn0 + r][m];
#pragma unroll
            for (int j = 0; j < 4; ++j) {
                const u64 v0 = *(const u64*)&sv[m + j][d0];
                const u64 v1 = *(const u64*)&sv[m + j][d0 + 2];
#pragma unroll
                for (int r = 0; r < 7; ++r) {
                    const float sj = (j == 0) ? s4[r].x : (j == 1) ? s4[r].y
                                   : (j == 2) ? s4[r].z : s4[r].w;
                    const u64 sd = dup32(sj);
                    acc2[r][0] = f2fma(sd, v0, acc2[r][0]);
                    acc2[r][1] = f2fma(sd, v1, acc2[r][1]);
                }
            }
        }
        {
            const u64 v0 = *(const u64*)&sv[48][d0];
            const u64 v1 = *(const u64*)&sv[48][d0 + 2];
#pragma unroll
            for (int r = 0; r < 7; ++r) {
                const u64 sd = dup32(s[nn0 + r][48]);
                acc2[r][0] = f2fma(sd, v0, acc2[r][0]);
                acc2[r][1] = f2fma(sd, v1, acc2[r][1]);
            }
        }

#pragma unroll
        for (int r = 0; r < 7; ++r) {
            const float inv = sinv[nn0 + r];
            unsigned short hh[4], ll[4];
#pragma unroll
            for (int cc = 0; cc < 2; ++cc) {
                const u64 a = acc2[r][cc];
                split_h(__uint_as_float((u32)(a & 0xffffffffull)) * inv, hh[2 * cc], ll[2 * cc]);
                split_h(__uint_as_float((u32)(a >> 32)) * inv, hh[2 * cc + 1], ll[2 * cc + 1]);
            }
            uint2 vh = make_uint2((u32)hh[0] | ((u32)hh[1] << 16), (u32)hh[2] | ((u32)hh[3] << 16));
            uint2 vl = make_uint2((u32)ll[0] | ((u32)ll[1] << 16), (u32)ll[2] | ((u32)ll[3] << 16));
            const size_t off = ((size_t)bwin * NTOK + nn0 + r) * 256 + h * 32 + d0;
            *(uint2*)(g_ahi + off) = vh;
            *(uint2*)(g_alo + off) = vl;
        }
    }
}

// ---------------- launch ----------------
extern "C" void kernel_launch(void* const* d_in, const int* in_sizes, int n_in,
                              void* d_out, int out_size) {
    const float* x      = (const float*)d_in[0];
    const float* qkv_w  = (const float*)d_in[1];
    const float* qkv_b  = (const float*)d_in[2];
    const float* proj_w = (const float*)d_in[3];
    const float* proj_b = (const float*)d_in[4];
    const float* table  = (const float*)d_in[5];
    const int*   rel    = (const int*)d_in[6];
    float* out = (float*)d_out;

    const int SM1 = NSTAGE * 2 * TILE_B;   // 61440
    const int SM2 = NSTAGE * 3 * TILE_B;   // 92160

    static int smem_set = 0;
    if (!smem_set) {
        cudaFuncSetAttribute(gemm_mma<0, 1>, cudaFuncAttributeMaxDynamicSharedMemorySize, SM1);
        cudaFuncSetAttribute(gemm_mma<1, 2>, cudaFuncAttributeMaxDynamicSharedMemorySize, SM2);
        smem_set = 1;
    }

    pre_kernel<<<(int)(((size_t)MTOT * DIM / 4 + 255) / 256), 256>>>(x, qkv_w, proj_w, table, rel);
    gemm_mma<0, 1><<<dim3(6, MTOT / 128), 512, SM1>>>(qkv_b, nullptr);
    attn_kernel<<<BWIN * NH, 64>>>();
    gemm_mma<1, 2><<<dim3(2, MTOT / 128), 512, SM2>>>(proj_b, out);
}